// round 9
// baseline (speedup 1.0000x reference)
#include <cuda_runtime.h>
#include <cuda_bf16.h>
#include <cstdint>

// Shapes (fixed)
#define Bb  4
#define Qq  100
#define Cc  81
#define Mm  50
#define HWN 65536

// Tiling
#define SPL 72            // K-splits per batch; grid = 72*4 = 288 CTAs, 2/SM
#define KC  64            // k-elements per stage

// bf16 tiles: rows stride 144B -> conflict-free ldmatrix
#define RS     144
#define SS_OFF (128 * RS)
#define TS_OFF (2 * 128 * RS)
#define STAGE  (2 * 128 * RS + 64 * RS)  // 46080
#define SMEM_BYTES (2 * STAGE)           // 92160 (x2 CTAs = 184KB/SM)

// -------- device scratch (static; no allocations) --------
__device__ float g_ax [Bb * Qq * Mm];   // x.t        (atomic accum)
__device__ float g_ath[Bb * Qq * Mm];   // tanh(x/2).t (atomic accum)
__device__ float g_sp [Bb * Qq];        // softplus row sums
__device__ float g_th [Bb * Qq];        // tanh row sums
__device__ float g_ts [Bb * Mm];        // t row sums
__device__ int   g_s64;                 // ids stored as int64?

__device__ __forceinline__ uint32_t s2u(const void* p) {
    uint32_t a;
    asm("{ .reg .u64 t; cvta.to.shared.u64 t, %1; cvt.u32.u64 %0, t; }" : "=r"(a) : "l"(p));
    return a;
}
__device__ __forceinline__ void ldsm4(uint32_t* r, uint32_t a) {
    asm volatile("ldmatrix.sync.aligned.m8n8.x4.shared.b16 {%0,%1,%2,%3}, [%4];"
                 : "=r"(r[0]), "=r"(r[1]), "=r"(r[2]), "=r"(r[3]) : "r"(a));
}
__device__ __forceinline__ void mma16816(float* c, const uint32_t* a, uint32_t b0, uint32_t b1) {
    asm volatile("mma.sync.aligned.m16n8k16.row.col.f32.bf16.bf16.f32 "
                 "{%0,%1,%2,%3}, {%4,%5,%6,%7}, {%8,%9}, {%0,%1,%2,%3};"
                 : "+f"(c[0]), "+f"(c[1]), "+f"(c[2]), "+f"(c[3])
                 : "r"(a[0]), "r"(a[1]), "r"(a[2]), "r"(a[3]), "r"(b0), "r"(b1));
}

// -------- prep: zero accumulators + parallel id-width detect --------
__global__ void prep_k(const unsigned int* __restrict__ ids) {
    const int i = blockIdx.x * blockDim.x + threadIdx.x;
    if (i < Bb * Qq * Mm) { g_ax[i] = 0.f; g_ath[i] = 0.f; }
    if (i < Bb * Qq)      { g_sp[i] = 0.f; g_th[i]  = 0.f; }
    if (i < Bb * Mm)      { g_ts[i] = 0.f; }
    if (blockIdx.x == 0) {
        __shared__ int flag;
        if (threadIdx.x == 0) flag = 1;
        __syncthreads();
        if (threadIdx.x < Bb * Mm / 2 && ids[2 * threadIdx.x + 1] != 0u) flag = 0;
        __syncthreads();
        if (threadIdx.x == 0) g_s64 = flag;
    }
}

// ================= fused convert + dual bf16 mma.sync GEMM =================
__global__ __launch_bounds__(256, 2)
void cost_main(const float* __restrict__ X, const float* __restrict__ T) {
    extern __shared__ char smem[];
    const uint32_t sm0 = s2u(smem);

    const int tid = threadIdx.x;
    const int l   = tid & 31;
    const int wid = tid >> 5;
    const int wr  = wid & 3;           // warp row 0..3; each SMSP: one wc=0 + one wc=1
    const int wc  = wid >> 2;          // warp col 0..1
    const int rb  = tid >> 4;          // 0..15 load row
    const int cg  = tid & 15;          // 0..15 column group (4 floats)
    const int mt  = (wr == 3) ? 1 : 2; // skip all-padding m16 tile (rows 112-127)
    const int nt  = wc ? 3 : 4;        // n8 tiles (cols >=56 skipped)

    const int split = blockIdx.x;
    const int b     = blockIdx.y;
    const int nst   = (split < 16) ? 15 : 14;
    const int k0    = (split * 14 + min(split, 16)) * KC;

    const float* Xb = X + (size_t)b * Qq * HWN;
    const float* Tb = T + (size_t)b * Mm * HWN;

    // ldmatrix per-lane base addresses
    const uint32_t sA0 = sm0 + (uint32_t)(wr * 32 + (l & 15)) * RS + ((l >> 4) & 1) * 16;
    const uint32_t sA1 = sA0 + 16 * RS;
    const uint32_t sS0 = sA0 + SS_OFF;
    const uint32_t sS1 = sA1 + SS_OFF;
    const uint32_t sB0 = sm0 + TS_OFF +
        (uint32_t)(wc * 32 + (l & 7) + ((l >> 4) & 1) * 8) * RS + ((l >> 3) & 1) * 16;
    const uint32_t sB1 = sB0 + 16 * RS;

    float accx[2][4][4], accs[2][4][4];
#pragma unroll
    for (int i = 0; i < 2; i++)
#pragma unroll
        for (int j = 0; j < 4; j++)
#pragma unroll
            for (int k = 0; k < 4; k++) { accx[i][j][k] = 0.f; accs[i][j][k] = 0.f; }

    float xa[7] = {0,0,0,0,0,0,0};   // sum x
    float ta[7] = {0,0,0,0,0,0,0};   // sum tanh(x/2)
    float la[7] = {0,0,0,0,0,0,0};   // sum lg2(sigmoid(x))
    float ts_acc[4] = {0,0,0,0};

    float4 rx[7], rt[4];
    // prologue: prefetch stage 0 into registers
    {
        const int kg = k0 + 4 * cg;
#pragma unroll
        for (int i = 0; i < 7; i++) {
            const int r = rb + 16 * i;
            if (r < Qq) rx[i] = *(const float4*)(Xb + (size_t)r * HWN + kg);
        }
#pragma unroll
        for (int i = 0; i < 4; i++) {
            const int r = rb + 16 * i;
            if (r < Mm) rt[i] = *(const float4*)(Tb + (size_t)r * HWN + kg);
        }
    }

    for (int s = 0; s < nst; s++) {
        const int buf = s & 1;
        char* const bufp = smem + buf * STAGE;

        // ---- convert staged regs -> bf16 smem: x and tanh(x/2) ----
#pragma unroll
        for (int i = 0; i < 7; i++) {
            const int r = rb + 16 * i;
            if (r < Qq) {
                const float xs[4] = {rx[i].x, rx[i].y, rx[i].z, rx[i].w};
                float tv[4];
#pragma unroll
                for (int j = 0; j < 4; j++) {
                    const float xx = xs[j];
                    float th;
                    asm("tanh.approx.f32 %0, %1;" : "=f"(th) : "f"(0.5f * xx));
                    tv[j] = th;
                    float lg;
                    asm("lg2.approx.f32 %0, %1;" : "=f"(lg) : "f"(fmaf(0.5f, th, 0.5f)));
                    xa[i] += xx; ta[i] += th; la[i] += lg;
                }
                __nv_bfloat162 hx0 = __float22bfloat162_rn(make_float2(xs[0], xs[1]));
                __nv_bfloat162 hx1 = __float22bfloat162_rn(make_float2(xs[2], xs[3]));
                __nv_bfloat162 ht0 = __float22bfloat162_rn(make_float2(tv[0], tv[1]));
                __nv_bfloat162 ht1 = __float22bfloat162_rn(make_float2(tv[2], tv[3]));
                char* const p = bufp + r * RS + cg * 8;
                *reinterpret_cast<uint2*>(p) =
                    make_uint2(*reinterpret_cast<uint32_t*>(&hx0), *reinterpret_cast<uint32_t*>(&hx1));
                *reinterpret_cast<uint2*>(p + SS_OFF) =
                    make_uint2(*reinterpret_cast<uint32_t*>(&ht0), *reinterpret_cast<uint32_t*>(&ht1));
            }
        }
#pragma unroll
        for (int i = 0; i < 4; i++) {
            const int r = rb + 16 * i;
            if (r < Mm) {
                const float4 w = rt[i];
                ts_acc[i] += w.x + w.y + w.z + w.w;
                __nv_bfloat162 h0 = __float22bfloat162_rn(make_float2(w.x, w.y));
                __nv_bfloat162 h1 = __float22bfloat162_rn(make_float2(w.z, w.w));
                *reinterpret_cast<uint2*>(bufp + TS_OFF + r * RS + cg * 8) =
                    make_uint2(*reinterpret_cast<uint32_t*>(&h0), *reinterpret_cast<uint32_t*>(&h1));
            }
        }

        // ---- prefetch next stage ----
        if (s + 1 < nst) {
            const int kg = k0 + (s + 1) * KC + 4 * cg;
#pragma unroll
            for (int i = 0; i < 7; i++) {
                const int r = rb + 16 * i;
                if (r < Qq) rx[i] = *(const float4*)(Xb + (size_t)r * HWN + kg);
            }
#pragma unroll
            for (int i = 0; i < 4; i++) {
                const int r = rb + 16 * i;
                if (r < Mm) rt[i] = *(const float4*)(Tb + (size_t)r * HWN + kg);
            }
        }

        __syncthreads();

        // ---- dual mma over KC=64 (4 k16-steps) ----
        const uint32_t boff = (uint32_t)buf * STAGE;
#pragma unroll
        for (int st = 0; st < 4; st++) {
            const uint32_t so = boff + st * 32;
            uint32_t ax0[4], ax1[4], as0[4], as1[4], bb0[4], bb1[4];
            ldsm4(ax0, sA0 + so);
            if (mt == 2) ldsm4(ax1, sA1 + so);
            ldsm4(as0, sS0 + so);
            if (mt == 2) ldsm4(as1, sS1 + so);
            ldsm4(bb0, sB0 + so); ldsm4(bb1, sB1 + so);
            const uint32_t bfr[4][2] = {{bb0[0], bb0[1]}, {bb0[2], bb0[3]},
                                        {bb1[0], bb1[1]}, {bb1[2], bb1[3]}};
#pragma unroll
            for (int fc = 0; fc < 4; fc++) {
                if (fc < nt) {
                    mma16816(accx[0][fc], ax0, bfr[fc][0], bfr[fc][1]);
                    mma16816(accs[0][fc], as0, bfr[fc][0], bfr[fc][1]);
                    if (mt == 2) {
                        mma16816(accx[1][fc], ax1, bfr[fc][0], bfr[fc][1]);
                        mma16816(accs[1][fc], as1, bfr[fc][0], bfr[fc][1]);
                    }
                }
            }
        }
        // single-sync 2-buffer safety: convert(s+1) targets the other buffer;
        // mma(s-1) on that buffer completed before this stage's barrier.
    }

    // ---- row-stat reductions (16 lanes share a row) -> atomic accum ----
#pragma unroll
    for (int i = 0; i < 7; i++) {
        float v1 = xa[i], v2 = ta[i], v3 = la[i];
#pragma unroll
        for (int off = 8; off; off >>= 1) {
            v1 += __shfl_down_sync(0xffffffffu, v1, off, 16);
            v2 += __shfl_down_sync(0xffffffffu, v2, off, 16);
            v3 += __shfl_down_sync(0xffffffffu, v3, off, 16);
        }
        const int r = rb + 16 * i;
        if (cg == 0 && r < Qq) {
            atomicAdd(&g_sp[b * Qq + r], v1 - 0.69314718f * v3);   // softplus
            atomicAdd(&g_th[b * Qq + r], v2);                      // sum tanh
        }
    }
#pragma unroll
    for (int i = 0; i < 4; i++) {
        float v = ts_acc[i];
#pragma unroll
        for (int off = 8; off; off >>= 1) v += __shfl_down_sync(0xffffffffu, v, off, 16);
        const int r = rb + 16 * i;
        if (cg == 0 && r < Mm) atomicAdd(&g_ts[b * Mm + r], v);
    }

    // ---- mma partials -> atomic accum into [B,Q,M] ----
    {
        const int ql = l >> 2;
        const int mo = 2 * (l & 3);
#pragma unroll
        for (int im = 0; im < 2; im++) {
            if (im < mt) {
#pragma unroll
                for (int fc = 0; fc < 4; fc++) {
                    if (fc < nt) {
                        const int m = wc * 32 + fc * 8 + mo;   // even; m+1 <= 49
                        if (m < Mm) {
                            const int q = wr * 32 + im * 16 + ql;
                            if (q < Qq) {
                                const int idx = (b * Qq + q) * Mm + m;
                                atomicAdd(&g_ax[idx],      accx[im][fc][0]);
                                atomicAdd(&g_ax[idx + 1],  accx[im][fc][1]);
                                atomicAdd(&g_ath[idx],     accs[im][fc][0]);
                                atomicAdd(&g_ath[idx + 1], accs[im][fc][1]);
                            }
                            if (q + 8 < Qq) {
                                const int idx = (b * Qq + q + 8) * Mm + m;
                                atomicAdd(&g_ax[idx],      accx[im][fc][2]);
                                atomicAdd(&g_ax[idx + 1],  accx[im][fc][3]);
                                atomicAdd(&g_ath[idx],     accs[im][fc][2]);
                                atomicAdd(&g_ath[idx + 1], accs[im][fc][3]);
                            }
                        }
                    }
                }
            }
        }
    }
}

// ================= finalize: softmax + assemble (all sums pre-reduced) =================
__global__ __launch_bounds__(128)
void finalize_k(const float* __restrict__ logits,
                const unsigned int* __restrict__ ids,
                float* __restrict__ out) {
    const int bq = blockIdx.x;           // 0..B*Q-1
    const int b  = bq / Qq;
    const int tid = threadIdx.x;
    __shared__ float se[Cc];
    __shared__ float sinv;

    if (tid < Cc) se[tid] = logits[bq * Cc + tid];
    __syncthreads();

    if (tid < 32) {
        float mx = -1e30f;
        for (int c = tid; c < Cc; c += 32) mx = fmaxf(mx, se[c]);
#pragma unroll
        for (int off = 16; off; off >>= 1) mx = fmaxf(mx, __shfl_xor_sync(0xffffffffu, mx, off));
        float sm = 0.f;
        for (int c = tid; c < Cc; c += 32) { const float e = __expf(se[c] - mx); se[c] = e; sm += e; }
#pragma unroll
        for (int off = 16; off; off >>= 1) sm += __shfl_xor_sync(0xffffffffu, sm, off);
        if (tid == 0) sinv = __fdividef(1.0f, sm);
    }
    __syncthreads();

    if (tid < Mm) {
        const int m = tid;
        const unsigned id = g_s64 ? ids[2 * (b * Mm + m)] : ids[b * Mm + m];
        const float prob    = se[id] * sinv;
        const float ax      = g_ax [bq * Mm + m];
        const float ath     = g_ath[bq * Mm + m];
        const float at      = g_ts [b * Mm + m];
        const float spm     = g_sp[bq] * (1.0f / (float)HWN);
        const float sig_dot = fmaf(0.5f, ath, 0.5f * at);             // sig(x).t
        const float sig_sum = fmaf(0.5f, g_th[bq], 0.5f * (float)HWN);
        const float denom   = sig_sum + at + 1e-6f;
        out[bq * Mm + m] = -prob + (spm - ax * (1.0f / (float)HWN)) + 1.0f - 2.0f * sig_dot / denom;
    }
}

extern "C" void kernel_launch(void* const* d_in, const int* in_sizes, int n_in,
                              void* d_out, int out_size) {
    const float*        logits = (const float*)d_in[0];        // [B,Q,C]
    const float*        pmask  = (const float*)d_in[1];        // [B,Q,H,W]
    const unsigned int* ids    = (const unsigned int*)d_in[2]; // [B,M] int32 or int64
    const float*        tmask  = (const float*)d_in[3];        // [B,M,H,W]
    float*              out    = (float*)d_out;                // [B,Q,M]

    cudaFuncSetAttribute(cost_main, cudaFuncAttributeMaxDynamicSharedMemorySize, SMEM_BYTES);
    dim3 grid(SPL, Bb);
    prep_k<<<(Bb * Qq * Mm + 255) / 256, 256>>>(ids);
    cost_main<<<grid, 256, SMEM_BYTES>>>(pmask, tmask);
    finalize_k<<<Bb * Qq, 128>>>(logits, ids, out);
}

// round 10
// speedup vs baseline: 2.5880x; 2.5880x over previous
#include <cuda_runtime.h>
#include <cuda_bf16.h>
#include <cstdint>

// Shapes (fixed)
#define Bb  4
#define Qq  100
#define Cc  81
#define Mm  50
#define HWN 65536

// Tiling
#define SPL 36            // K-splits per batch; grid = 36 x 4 = 144 CTAs (1 wave)
#define KC  64            // k-elements per stage
#define PW2 52            // padded m-width in scratch

// bf16 tiles: rows stride 144B -> conflict-free ldmatrix
#define RS     144
#define SS_OFF (128 * RS)
#define TS_OFF (2 * 128 * RS)
#define STAGE  (2 * 128 * RS + 64 * RS)  // 46080
#define SMEM_BYTES (2 * STAGE)           // 92160

// -------- device scratch (static; no allocations) --------
// transposed for coalesced finalize reads: [(b,q), split, ...]
__device__ float g_px[(size_t)Bb * Qq * SPL * PW2];  // x.t partials
__device__ float g_ps[(size_t)Bb * Qq * SPL * PW2];  // tanh(x/2).t partials
__device__ float g_spp[Bb * Qq * SPL];               // softplus row partials
__device__ float g_sgp[Bb * Qq * SPL];               // tanh row partials
__device__ float g_tsp[Bb * SPL * Mm];               // t row partials

__device__ __forceinline__ uint32_t s2u(const void* p) {
    uint32_t a;
    asm("{ .reg .u64 t; cvta.to.shared.u64 t, %1; cvt.u32.u64 %0, t; }" : "=r"(a) : "l"(p));
    return a;
}
__device__ __forceinline__ void ldsm4(uint32_t* r, uint32_t a) {
    asm volatile("ldmatrix.sync.aligned.m8n8.x4.shared.b16 {%0,%1,%2,%3}, [%4];"
                 : "=r"(r[0]), "=r"(r[1]), "=r"(r[2]), "=r"(r[3]) : "r"(a));
}
__device__ __forceinline__ void mma16816(float* c, const uint32_t* a, uint32_t b0, uint32_t b1) {
    asm volatile("mma.sync.aligned.m16n8k16.row.col.f32.bf16.bf16.f32 "
                 "{%0,%1,%2,%3}, {%4,%5,%6,%7}, {%8,%9}, {%0,%1,%2,%3};"
                 : "+f"(c[0]), "+f"(c[1]), "+f"(c[2]), "+f"(c[3])
                 : "r"(a[0]), "r"(a[1]), "r"(a[2]), "r"(a[3]), "r"(b0), "r"(b1));
}

// ================= fused convert + dual bf16 mma.sync GEMM =================
__global__ __launch_bounds__(256, 1)
void cost_main(const float* __restrict__ X, const float* __restrict__ T) {
    extern __shared__ char smem[];
    const uint32_t sm0 = s2u(smem);

    const int tid = threadIdx.x;
    const int l   = tid & 31;
    const int wid = tid >> 5;
    const int wr  = wid & 3;           // warp row 0..3; each SMSP: one wc=0 + one wc=1
    const int wc  = wid >> 2;          // warp col 0..1  (n-cols 0-31 / 32-55)
    const int rb  = tid >> 4;          // 0..15 load row
    const int cg  = tid & 15;          // 0..15 column group (4 floats)
    const int mt  = (wr == 3) ? 1 : 2; // skip all-padding m16 tile (rows 112-127)
    const int nt  = wc ? 3 : 4;        // n8 tiles (cols >= 56 skipped)

    const int split = blockIdx.x;
    const int b     = blockIdx.y;
    const int nst   = (split < 16) ? 29 : 28;
    const int k0    = (split * 28 + min(split, 16)) * KC;

    const float* Xb = X + (size_t)b * Qq * HWN;
    const float* Tb = T + (size_t)b * Mm * HWN;

    // ldmatrix per-lane base addresses (canonical m8n8.x4 patterns)
    const uint32_t sA0 = sm0 + (uint32_t)(wr * 32 + (l & 15)) * RS + ((l >> 4) & 1) * 16;
    const uint32_t sA1 = sA0 + 16 * RS;
    const uint32_t sS0 = sA0 + SS_OFF;
    const uint32_t sS1 = sA1 + SS_OFF;
    const uint32_t sB0 = sm0 + TS_OFF +
        (uint32_t)(wc * 32 + (l & 7) + ((l >> 4) & 1) * 8) * RS + ((l >> 3) & 1) * 16;
    const uint32_t sB1 = sB0 + 16 * RS;

    float accx[2][4][4], accs[2][4][4];
#pragma unroll
    for (int i = 0; i < 2; i++)
#pragma unroll
        for (int j = 0; j < 4; j++)
#pragma unroll
            for (int k = 0; k < 4; k++) { accx[i][j][k] = 0.f; accs[i][j][k] = 0.f; }

    float xa[7] = {0,0,0,0,0,0,0};   // sum x
    float ta[7] = {0,0,0,0,0,0,0};   // sum tanh(x/2)
    float la[7] = {0,0,0,0,0,0,0};   // sum lg2(sigmoid(x))
    float ts_acc[4] = {0,0,0,0};

    float4 rx[7], rt[4];
    // prologue: prefetch stage 0 into registers
    {
        const int kg = k0 + 4 * cg;
#pragma unroll
        for (int i = 0; i < 7; i++) {
            const int r = rb + 16 * i;
            if (r < Qq) rx[i] = *(const float4*)(Xb + (size_t)r * HWN + kg);
        }
#pragma unroll
        for (int i = 0; i < 4; i++) {
            const int r = rb + 16 * i;
            if (r < Mm) rt[i] = *(const float4*)(Tb + (size_t)r * HWN + kg);
        }
    }

    for (int s = 0; s < nst; s++) {
        const int buf = s & 1;
        char* const bufp = smem + buf * STAGE;

        // ---- convert staged regs -> bf16 smem: x and tanh(x/2) ----
#pragma unroll
        for (int i = 0; i < 7; i++) {
            const int r = rb + 16 * i;
            if (r < Qq) {
                const float xs[4] = {rx[i].x, rx[i].y, rx[i].z, rx[i].w};
                float tv[4];
#pragma unroll
                for (int j = 0; j < 4; j++) {
                    const float xx = xs[j];
                    float th;
                    asm("tanh.approx.f32 %0, %1;" : "=f"(th) : "f"(0.5f * xx));
                    tv[j] = th;
                    float lg;
                    asm("lg2.approx.f32 %0, %1;" : "=f"(lg) : "f"(fmaf(0.5f, th, 0.5f)));
                    xa[i] += xx; ta[i] += th; la[i] += lg;
                }
                __nv_bfloat162 hx0 = __float22bfloat162_rn(make_float2(xs[0], xs[1]));
                __nv_bfloat162 hx1 = __float22bfloat162_rn(make_float2(xs[2], xs[3]));
                __nv_bfloat162 ht0 = __float22bfloat162_rn(make_float2(tv[0], tv[1]));
                __nv_bfloat162 ht1 = __float22bfloat162_rn(make_float2(tv[2], tv[3]));
                char* const p = bufp + r * RS + cg * 8;
                *reinterpret_cast<uint2*>(p) =
                    make_uint2(*reinterpret_cast<uint32_t*>(&hx0), *reinterpret_cast<uint32_t*>(&hx1));
                *reinterpret_cast<uint2*>(p + SS_OFF) =
                    make_uint2(*reinterpret_cast<uint32_t*>(&ht0), *reinterpret_cast<uint32_t*>(&ht1));
            }
        }
#pragma unroll
        for (int i = 0; i < 4; i++) {
            const int r = rb + 16 * i;
            if (r < Mm) {
                const float4 w = rt[i];
                ts_acc[i] += w.x + w.y + w.z + w.w;
                __nv_bfloat162 h0 = __float22bfloat162_rn(make_float2(w.x, w.y));
                __nv_bfloat162 h1 = __float22bfloat162_rn(make_float2(w.z, w.w));
                *reinterpret_cast<uint2*>(bufp + TS_OFF + r * RS + cg * 8) =
                    make_uint2(*reinterpret_cast<uint32_t*>(&h0), *reinterpret_cast<uint32_t*>(&h1));
            }
        }

        // ---- prefetch next stage (in flight across the mma phase) ----
        if (s + 1 < nst) {
            const int kg = k0 + (s + 1) * KC + 4 * cg;
#pragma unroll
            for (int i = 0; i < 7; i++) {
                const int r = rb + 16 * i;
                if (r < Qq) rx[i] = *(const float4*)(Xb + (size_t)r * HWN + kg);
            }
#pragma unroll
            for (int i = 0; i < 4; i++) {
                const int r = rb + 16 * i;
                if (r < Mm) rt[i] = *(const float4*)(Tb + (size_t)r * HWN + kg);
            }
        }

        __syncthreads();

        // ---- dual mma over KC=64 (4 k16-steps) ----
        const uint32_t boff = (uint32_t)buf * STAGE;
#pragma unroll
        for (int st = 0; st < 4; st++) {
            const uint32_t so = boff + st * 32;
            uint32_t ax0[4], ax1[4], as0[4], as1[4], bb0[4], bb1[4];
            ldsm4(ax0, sA0 + so);
            if (mt == 2) ldsm4(ax1, sA1 + so);
            ldsm4(as0, sS0 + so);
            if (mt == 2) ldsm4(as1, sS1 + so);
            ldsm4(bb0, sB0 + so); ldsm4(bb1, sB1 + so);
            const uint32_t bfr[4][2] = {{bb0[0], bb0[1]}, {bb0[2], bb0[3]},
                                        {bb1[0], bb1[1]}, {bb1[2], bb1[3]}};
#pragma unroll
            for (int fc = 0; fc < 4; fc++) {
                if (fc < nt) {
                    mma16816(accx[0][fc], ax0, bfr[fc][0], bfr[fc][1]);
                    mma16816(accs[0][fc], as0, bfr[fc][0], bfr[fc][1]);
                    if (mt == 2) {
                        mma16816(accx[1][fc], ax1, bfr[fc][0], bfr[fc][1]);
                        mma16816(accs[1][fc], as1, bfr[fc][0], bfr[fc][1]);
                    }
                }
            }
        }
        // 2-buffer, 1-sync safety: convert(s+1) writes the other buffer; the
        // barrier orders buffer reuse two stages apart.
    }

    // ---- row-stat reductions (16 lanes share a row) -> scratch ----
#pragma unroll
    for (int i = 0; i < 7; i++) {
        float v1 = xa[i], v2 = ta[i], v3 = la[i];
#pragma unroll
        for (int off = 8; off; off >>= 1) {
            v1 += __shfl_down_sync(0xffffffffu, v1, off, 16);
            v2 += __shfl_down_sync(0xffffffffu, v2, off, 16);
            v3 += __shfl_down_sync(0xffffffffu, v3, off, 16);
        }
        const int r = rb + 16 * i;
        if (cg == 0 && r < Qq) {
            g_spp[(b * Qq + r) * SPL + split] = v1 - 0.69314718f * v3;   // softplus
            g_sgp[(b * Qq + r) * SPL + split] = v2;                      // sum tanh
        }
    }
#pragma unroll
    for (int i = 0; i < 4; i++) {
        float v = ts_acc[i];
#pragma unroll
        for (int off = 8; off; off >>= 1) v += __shfl_down_sync(0xffffffffu, v, off, 16);
        const int r = rb + 16 * i;
        if (cg == 0 && r < Mm) g_tsp[(b * SPL + split) * Mm + r] = v;
    }

    // ---- write mma partials: [(b,q), split, m] ----
    {
        const int ql = l >> 2;
        const int mo = 2 * (l & 3);
#pragma unroll
        for (int im = 0; im < 2; im++) {
            if (im < mt) {
#pragma unroll
                for (int fc = 0; fc < 4; fc++) {
                    if (fc < nt) {
                        const int m = wc * 32 + fc * 8 + mo;
                        if (m < Mm) {
                            const int q = wr * 32 + im * 16 + ql;
                            if (q < Qq) {
                                const size_t idx = ((size_t)(b * Qq + q) * SPL + split) * PW2 + m;
                                *(float2*)&g_px[idx] = make_float2(accx[im][fc][0], accx[im][fc][1]);
                                *(float2*)&g_ps[idx] = make_float2(accs[im][fc][0], accs[im][fc][1]);
                            }
                            if (q + 8 < Qq) {
                                const size_t idx = ((size_t)(b * Qq + q + 8) * SPL + split) * PW2 + m;
                                *(float2*)&g_px[idx] = make_float2(accx[im][fc][2], accx[im][fc][3]);
                                *(float2*)&g_ps[idx] = make_float2(accs[im][fc][2], accs[im][fc][3]);
                            }
                        }
                    }
                }
            }
        }
    }
}

// ================= finalize: coalesced reduce + softmax + assemble =================
// g_ps holds tanh-dot; sig.t = 0.5*tanh_dot + 0.5*Sum(t)
__global__ __launch_bounds__(512)
void finalize_k(const float* __restrict__ logits,
                const unsigned int* __restrict__ ids,
                float* __restrict__ out) {
    const int bq = blockIdx.x;           // 0..B*Q-1
    const int b  = bq / Qq;
    const int tid = threadIdx.x;
    __shared__ float se[Cc];
    __shared__ __align__(16) float sx[SPL][PW2];
    __shared__ __align__(16) float ss_[SPL][PW2];
    __shared__ float spv[SPL], sgv[SPL];
    __shared__ float sinv, ssp, ssg;
    __shared__ int s64;

    if (tid == 0) s64 = 1;
    if (tid < Cc) se[tid] = logits[bq * Cc + tid];
    if (tid < 100 && ids[2 * tid + 1] != 0u) s64 = 0;   // int64 high words all zero

    // coalesced bulk load of this (b,q)'s partials: 36 splits x 52 floats
    if (tid < SPL * 13) {
        const int s = tid / 13, c = (tid % 13) * 4;
        const size_t base = ((size_t)bq * SPL + s) * PW2 + c;
        *(float4*)&sx[s][c]  = *(const float4*)&g_px[base];
        *(float4*)&ss_[s][c] = *(const float4*)&g_ps[base];
    }
    if (tid >= 468 && tid < 468 + SPL) {
        const int s = tid - 468;
        spv[s] = g_spp[(size_t)bq * SPL + s];
        sgv[s] = g_sgp[(size_t)bq * SPL + s];
    }
    __syncthreads();

    // warp 0: parallel softmax over 81 classes
    if (tid < 32) {
        float mx = -1e30f;
        for (int c = tid; c < Cc; c += 32) mx = fmaxf(mx, se[c]);
#pragma unroll
        for (int off = 16; off; off >>= 1) mx = fmaxf(mx, __shfl_xor_sync(0xffffffffu, mx, off));
        float sm = 0.f;
        for (int c = tid; c < Cc; c += 32) { const float e = __expf(se[c] - mx); se[c] = e; sm += e; }
#pragma unroll
        for (int off = 16; off; off >>= 1) sm += __shfl_xor_sync(0xffffffffu, sm, off);
        if (tid == 0) sinv = __fdividef(1.0f, sm);
    }
    // per-q totals over splits
    if (tid == 62) { float v = 0.f; for (int s = 0; s < SPL; s++) v += spv[s]; ssp = v; }
    if (tid == 63) { float v = 0.f; for (int s = 0; s < SPL; s++) v += sgv[s]; ssg = v; }

    // per-m sums over splits (regs of tid<50)
    float ax = 0.f, ath = 0.f, at = 0.f;
    if (tid < Mm) {
#pragma unroll
        for (int s = 0; s < SPL; s++) {
            ax  += sx[s][tid];
            ath += ss_[s][tid];
            at  += g_tsp[(b * SPL + s) * Mm + tid];
        }
    }
    __syncthreads();

    if (tid < Mm) {
        const int m = tid;
        const unsigned id = s64 ? ids[2 * (b * Mm + m)] : ids[b * Mm + m];
        const float prob    = se[id] * sinv;
        const float spm     = ssp * (1.0f / (float)HWN);
        const float sig_dot = fmaf(0.5f, ath, 0.5f * at);               // sig(x).t
        const float sig_sum = fmaf(0.5f, ssg, 0.5f * (float)HWN);       // sum sig
        const float denom   = sig_sum + at + 1e-6f;
        out[bq * Mm + m] = -prob + (spm - ax * (1.0f / (float)HWN)) + 1.0f - 2.0f * sig_dot / denom;
    }
}

extern "C" void kernel_launch(void* const* d_in, const int* in_sizes, int n_in,
                              void* d_out, int out_size) {
    const float*        logits = (const float*)d_in[0];        // [B,Q,C]
    const float*        pmask  = (const float*)d_in[1];        // [B,Q,H,W]
    const unsigned int* ids    = (const unsigned int*)d_in[2]; // [B,M] int32 or int64
    const float*        tmask  = (const float*)d_in[3];        // [B,M,H,W]
    float*              out    = (float*)d_out;                // [B,Q,M]

    cudaFuncSetAttribute(cost_main, cudaFuncAttributeMaxDynamicSharedMemorySize, SMEM_BYTES);
    dim3 grid(SPL, Bb);
    cost_main<<<grid, 256, SMEM_BYTES>>>(pmask, tmask);
    finalize_k<<<Bb * Qq, 512>>>(logits, ids, out);
}